// round 1
// baseline (speedup 1.0000x reference)
#include <cuda_runtime.h>
#include <cuda_bf16.h>
#include <math.h>

// Problem constants
#define S_LEN 2048
#define BATCH 2
#define DMODEL 512
#define NHEAD 8
#define HDIM 64
#define FFDIM 2048
#define NTOK (S_LEN * BATCH)   // 4096
#define WWIN 5
#define LN_EPS 1e-5f

// ---------------- scratch (no allocations allowed) ----------------
__device__ float g_q[(size_t)BATCH * NHEAD * S_LEN * HDIM];     // 8 MB
__device__ float g_k[(size_t)BATCH * NHEAD * S_LEN * HDIM];
__device__ float g_v[(size_t)BATCH * NHEAD * S_LEN * HDIM];
__device__ float g_attn[(size_t)NTOK * DMODEL];                  // [S,B,D]
__device__ float g_tmp[(size_t)NTOK * DMODEL];
__device__ float g_x1[(size_t)NTOK * DMODEL];
__device__ float g_x2[(size_t)NTOK * DMODEL];
__device__ float g_ff[(size_t)NTOK * FFDIM];                     // 32 MB

// epilogue flags
#define EF_RELU    1
#define EF_HEADOUT 2
#define EF_RES     4

// ---------------- generic SGEMM: C[m,n] = sum_k A[m,k] * Bw[n,k] ----------------
// A: [M,K] row-major, Bw: [N,K] row-major (i.e. Y = A @ Bw^T), bias[n] always added.
// flags: EF_RELU -> relu; EF_RES -> += res[m*N+n]; EF_HEADOUT -> write to [B,H,S,HDIM].
#define BM 64
#define BN 64
#define BKT 16

__global__ __launch_bounds__(256) void sgemm_kernel(
    const float* __restrict__ A, const float* __restrict__ Bw,
    const float* __restrict__ bias, const float* __restrict__ res,
    float* __restrict__ C, int M, int N, int K, int flags)
{
    __shared__ float As[BKT][BM];
    __shared__ float Bs[BKT][BN];

    const int tx = threadIdx.x & 15;      // 0..15 (n dir)
    const int ty = threadIdx.x >> 4;      // 0..15 (m dir)
    const int lrow = threadIdx.x >> 2;    // 0..63 load row
    const int lcol4 = threadIdx.x & 3;    // 0..3  load col group

    const int bm = blockIdx.y * BM;
    const int bn = blockIdx.x * BN;

    const float* Aptr = A + (size_t)(bm + lrow) * K + lcol4 * 4;
    const float* Bptr = Bw + (size_t)(bn + lrow) * K + lcol4 * 4;

    float acc[4][4];
#pragma unroll
    for (int i = 0; i < 4; i++)
#pragma unroll
        for (int j = 0; j < 4; j++) acc[i][j] = 0.f;

    for (int k0 = 0; k0 < K; k0 += BKT) {
        float4 a = *(const float4*)(Aptr + k0);
        float4 b = *(const float4*)(Bptr + k0);
        __syncthreads();
        As[lcol4 * 4 + 0][lrow] = a.x;
        As[lcol4 * 4 + 1][lrow] = a.y;
        As[lcol4 * 4 + 2][lrow] = a.z;
        As[lcol4 * 4 + 3][lrow] = a.w;
        Bs[lcol4 * 4 + 0][lrow] = b.x;
        Bs[lcol4 * 4 + 1][lrow] = b.y;
        Bs[lcol4 * 4 + 2][lrow] = b.z;
        Bs[lcol4 * 4 + 3][lrow] = b.w;
        __syncthreads();
#pragma unroll
        for (int kk = 0; kk < BKT; kk++) {
            float4 av = *(const float4*)&As[kk][ty * 4];
            float4 bv = *(const float4*)&Bs[kk][tx * 4];
            acc[0][0] += av.x * bv.x; acc[0][1] += av.x * bv.y;
            acc[0][2] += av.x * bv.z; acc[0][3] += av.x * bv.w;
            acc[1][0] += av.y * bv.x; acc[1][1] += av.y * bv.y;
            acc[1][2] += av.y * bv.z; acc[1][3] += av.y * bv.w;
            acc[2][0] += av.z * bv.x; acc[2][1] += av.z * bv.y;
            acc[2][2] += av.z * bv.z; acc[2][3] += av.z * bv.w;
            acc[3][0] += av.w * bv.x; acc[3][1] += av.w * bv.y;
            acc[3][2] += av.w * bv.z; acc[3][3] += av.w * bv.w;
        }
    }

#pragma unroll
    for (int i = 0; i < 4; i++) {
        const int m = bm + ty * 4 + i;
#pragma unroll
        for (int j = 0; j < 4; j++) {
            const int n = bn + tx * 4 + j;
            float v = acc[i][j] + bias[n];
            if (flags & EF_RELU) v = fmaxf(v, 0.f);
            if (flags & EF_RES)  v += res[(size_t)m * N + n];
            if (flags & EF_HEADOUT) {
                // token m = s*B + b ; feature n = h*64 + hd  ->  [b][h][s][hd]
                const int s = m >> 1;          // BATCH == 2
                const int bidx = m & 1;
                const int h = n >> 6;
                const int hd = n & 63;
                g_q[0]; // no-op keep compiler quiet about unused
                C[(((size_t)(bidx * NHEAD + h)) * S_LEN + s) * HDIM + hd] = v;
            } else {
                C[(size_t)m * N + n] = v;
            }
        }
    }
}

// ---------------- sparse-mask attention, warp per query ----------------
// Q,K,V: [B*H, S, 64]. O: [S, B, D] (heads re-interleaved).
// allowed(j | i) = |j - i| <= 5  OR  j % 10 == 0
__global__ __launch_bounds__(256) void attn_kernel(
    const float* __restrict__ Q, const float* __restrict__ K,
    const float* __restrict__ V, float* __restrict__ O)
{
    const int warp = (blockIdx.x * blockDim.x + threadIdx.x) >> 5;
    const int lane = threadIdx.x & 31;
    const int i = warp & (S_LEN - 1);
    const int bh = warp >> 11;            // S_LEN = 2048 = 2^11
    const size_t base = (size_t)bh * S_LEN;

    const float2 q2 = ((const float2*)(Q + (base + i) * HDIM))[lane];

    float m = -1e30f, lsum = 0.f, accx = 0.f, accy = 0.f;

    auto process = [&](int j) {
        const float2 k2 = ((const float2*)(K + (base + j) * HDIM))[lane];
        float p = q2.x * k2.x + q2.y * k2.y;
        p += __shfl_xor_sync(0xffffffffu, p, 16);
        p += __shfl_xor_sync(0xffffffffu, p, 8);
        p += __shfl_xor_sync(0xffffffffu, p, 4);
        p += __shfl_xor_sync(0xffffffffu, p, 2);
        p += __shfl_xor_sync(0xffffffffu, p, 1);
        const float s = p * 0.125f;                    // 1/sqrt(64)
        const float nm = fmaxf(m, s);
        const float so = __expf(m - nm);
        const float e  = __expf(s - nm);
        const float2 v2 = ((const float2*)(V + (base + j) * HDIM))[lane];
        lsum = lsum * so + e;
        accx = accx * so + e * v2.x;
        accy = accy * so + e * v2.y;
        m = nm;
    };

    // strided keys: j % 10 == 0 (205 keys)
    for (int j = 0; j < S_LEN; j += 10) process(j);
    // band keys not already counted
    const int jlo = max(0, i - WWIN);
    const int jhi = min(S_LEN - 1, i + WWIN);
    for (int j = jlo; j <= jhi; j++)
        if (j % 10) process(j);

    const float inv = 1.f / lsum;
    const int b = bh >> 3;                 // NHEAD == 8
    const int h = bh & 7;
    float2 o2 = make_float2(accx * inv, accy * inv);
    ((float2*)(O + ((size_t)i * BATCH + b) * DMODEL + h * HDIM))[lane] = o2;
}

// ---------------- layernorm, block per row ----------------
__global__ __launch_bounds__(128) void ln_kernel(
    const float* __restrict__ in, const float* __restrict__ g,
    const float* __restrict__ b, float* __restrict__ out)
{
    const int row = blockIdx.x;
    const int t = threadIdx.x;
    const float4 v = ((const float4*)(in + (size_t)row * DMODEL))[t];

    float s  = v.x + v.y + v.z + v.w;
    float ss = v.x * v.x + v.y * v.y + v.z * v.z + v.w * v.w;
#pragma unroll
    for (int off = 16; off; off >>= 1) {
        s  += __shfl_xor_sync(0xffffffffu, s, off);
        ss += __shfl_xor_sync(0xffffffffu, ss, off);
    }
    __shared__ float red[8];
    const int wid = t >> 5;
    if ((t & 31) == 0) { red[wid] = s; red[4 + wid] = ss; }
    __syncthreads();
    s  = red[0] + red[1] + red[2] + red[3];
    ss = red[4] + red[5] + red[6] + red[7];

    const float mean = s * (1.f / DMODEL);
    const float var  = ss * (1.f / DMODEL) - mean * mean;
    const float r = rsqrtf(var + LN_EPS);

    const float4 gg = ((const float4*)g)[t];
    const float4 bb = ((const float4*)b)[t];
    float4 o;
    o.x = (v.x - mean) * r * gg.x + bb.x;
    o.y = (v.y - mean) * r * gg.y + bb.y;
    o.z = (v.z - mean) * r * gg.z + bb.z;
    o.w = (v.w - mean) * r * gg.w + bb.w;
    ((float4*)(out + (size_t)row * DMODEL))[t] = o;
}

// ---------------- launch ----------------
extern "C" void kernel_launch(void* const* d_in, const int* in_sizes, int n_in,
                              void* d_out, int out_size)
{
    const float* x   = (const float*)d_in[0];
    const float* enc = (const float*)d_in[1];
    const float* sa_Wq = (const float*)d_in[2];
    const float* sa_Wk = (const float*)d_in[3];
    const float* sa_Wv = (const float*)d_in[4];
    const float* sa_Wo = (const float*)d_in[5];
    const float* sa_bq = (const float*)d_in[6];
    const float* sa_bk = (const float*)d_in[7];
    const float* sa_bv = (const float*)d_in[8];
    const float* sa_bo = (const float*)d_in[9];
    const float* ca_Wq = (const float*)d_in[10];
    const float* ca_Wk = (const float*)d_in[11];
    const float* ca_Wv = (const float*)d_in[12];
    const float* ca_Wo = (const float*)d_in[13];
    const float* ca_bq = (const float*)d_in[14];
    const float* ca_bk = (const float*)d_in[15];
    const float* ca_bv = (const float*)d_in[16];
    const float* ca_bo = (const float*)d_in[17];
    const float* ff_W1 = (const float*)d_in[18];
    const float* ff_W2 = (const float*)d_in[19];
    const float* ff_b1 = (const float*)d_in[20];
    const float* ff_b2 = (const float*)d_in[21];
    const float* ln1_g = (const float*)d_in[22];
    const float* ln1_b = (const float*)d_in[23];
    const float* ln2_g = (const float*)d_in[24];
    const float* ln2_b = (const float*)d_in[25];
    const float* ln3_g = (const float*)d_in[26];
    const float* ln3_b = (const float*)d_in[27];
    float* out = (float*)d_out;

    float *q, *k, *v, *attn, *tmp, *x1, *x2, *ff;
    cudaGetSymbolAddress((void**)&q, g_q);
    cudaGetSymbolAddress((void**)&k, g_k);
    cudaGetSymbolAddress((void**)&v, g_v);
    cudaGetSymbolAddress((void**)&attn, g_attn);
    cudaGetSymbolAddress((void**)&tmp, g_tmp);
    cudaGetSymbolAddress((void**)&x1, g_x1);
    cudaGetSymbolAddress((void**)&x2, g_x2);
    cudaGetSymbolAddress((void**)&ff, g_ff);

    const dim3 blk(256);
    const dim3 gProj(DMODEL / BN, NTOK / BM);   // (8, 64)
    const dim3 gFF1(FFDIM / BN, NTOK / BM);     // (32, 64)
    const dim3 gAttn(BATCH * NHEAD * S_LEN / 8); // 8 warps/block -> 4096 blocks

    // ---- self attention ----
    sgemm_kernel<<<gProj, blk>>>(x, sa_Wq, sa_bq, nullptr, q, NTOK, DMODEL, DMODEL, EF_HEADOUT);
    sgemm_kernel<<<gProj, blk>>>(x, sa_Wk, sa_bk, nullptr, k, NTOK, DMODEL, DMODEL, EF_HEADOUT);
    sgemm_kernel<<<gProj, blk>>>(x, sa_Wv, sa_bv, nullptr, v, NTOK, DMODEL, DMODEL, EF_HEADOUT);
    attn_kernel<<<gAttn, blk>>>(q, k, v, attn);
    sgemm_kernel<<<gProj, blk>>>(attn, sa_Wo, sa_bo, x, tmp, NTOK, DMODEL, DMODEL, EF_RES);
    ln_kernel<<<NTOK, 128>>>(tmp, ln1_g, ln1_b, x1);

    // ---- cross attention ----
    sgemm_kernel<<<gProj, blk>>>(x1, ca_Wq, ca_bq, nullptr, q, NTOK, DMODEL, DMODEL, EF_HEADOUT);
    sgemm_kernel<<<gProj, blk>>>(enc, ca_Wk, ca_bk, nullptr, k, NTOK, DMODEL, DMODEL, EF_HEADOUT);
    sgemm_kernel<<<gProj, blk>>>(enc, ca_Wv, ca_bv, nullptr, v, NTOK, DMODEL, DMODEL, EF_HEADOUT);
    attn_kernel<<<gAttn, blk>>>(q, k, v, attn);
    sgemm_kernel<<<gProj, blk>>>(attn, ca_Wo, ca_bo, x1, tmp, NTOK, DMODEL, DMODEL, EF_RES);
    ln_kernel<<<NTOK, 128>>>(tmp, ln2_g, ln2_b, x2);

    // ---- feed forward ----
    sgemm_kernel<<<gFF1, blk>>>(x2, ff_W1, ff_b1, nullptr, ff, NTOK, FFDIM, DMODEL, EF_RELU);
    sgemm_kernel<<<gProj, blk>>>(ff, ff_W2, ff_b2, x2, tmp, NTOK, DMODEL, FFDIM, EF_RES);
    ln_kernel<<<NTOK, 128>>>(tmp, ln3_g, ln3_b, out);
}

// round 3
// speedup vs baseline: 2.0924x; 2.0924x over previous
#include <cuda_runtime.h>
#include <cuda_bf16.h>
#include <math.h>
#include <stdint.h>

// Problem constants
#define S_LEN 2048
#define BATCH 2
#define DMODEL 512
#define NHEAD 8
#define HDIM 64
#define FFDIM 2048
#define NTOK (S_LEN * BATCH)   // 4096
#define WWIN 5
#define LN_EPS 1e-5f

// ---------------- scratch (no allocations allowed) ----------------
__device__ float g_q[(size_t)BATCH * NHEAD * S_LEN * HDIM];
__device__ float g_k[(size_t)BATCH * NHEAD * S_LEN * HDIM];
__device__ float g_v[(size_t)BATCH * NHEAD * S_LEN * HDIM];
__device__ float g_attn[(size_t)NTOK * DMODEL];   // rounded tf32, feeds Wo GEMM
__device__ float g_tmp[(size_t)NTOK * DMODEL];
__device__ float g_x1[(size_t)NTOK * DMODEL];
__device__ float g_x2[(size_t)NTOK * DMODEL];
__device__ float g_ff[(size_t)NTOK * FFDIM];      // rounded tf32 (epilogue)
// rounded tf32 copies for MMA inputs
__device__ float g_wr[4194304];                    // 8 proj weights + ff_W1 + ff_W2
__device__ float g_xr[(size_t)NTOK * DMODEL];
__device__ float g_encr[(size_t)NTOK * DMODEL];
__device__ float g_x1r[(size_t)NTOK * DMODEL];
__device__ float g_x2r[(size_t)NTOK * DMODEL];

// epilogue flags
#define EF_RELU    1
#define EF_HEADOUT 2
#define EF_RES     4
#define EF_ROUND   8

__device__ __forceinline__ float tf32_rna(float x) {
    uint32_t u;
    asm("cvt.rna.tf32.f32 %0, %1;" : "=r"(u) : "f"(x));
    return __uint_as_float(u);
}

// ---------------- tf32 -> rounded-copy kernel ----------------
struct CvtArgs {
    const float* src[12];
    float* dst[12];
    int n4[12]; // element count / 4
};

__global__ __launch_bounds__(256) void cvt_kernel(CvtArgs args) {
    const int ti = blockIdx.y;
    const int n4 = args.n4[ti];
    const float4* src = (const float4*)args.src[ti];
    float4* dst = (float4*)args.dst[ti];
    for (int i = blockIdx.x * 256 + threadIdx.x; i < n4; i += gridDim.x * 256) {
        float4 v = src[i];
        v.x = tf32_rna(v.x); v.y = tf32_rna(v.y);
        v.z = tf32_rna(v.z); v.w = tf32_rna(v.w);
        dst[i] = v;
    }
}

// ---------------- tf32 tensor-core GEMM ----------------
// C[m,n] = sum_k A[m,k] * Bw[n,k]  (Y = A @ Bw^T), bias[n] added.
// A: [M,K] row-major (tf32-rounded), Bw: [N,K] row-major (tf32-rounded).
// BM=128, BN=64, BK=32, 256 threads, 8 warps (4M x 2N), warp tile 32x32.
#define GBM 128
#define GBN 64
#define GBK 32
#define APAD 36   // padded row stride (floats) for conflict-free fragment LDS
#define A_BUF (GBM * APAD)   // 4608 floats
#define B_BUF (GBN * APAD)   // 2304 floats
#define GEMM_SMEM_BYTES ((2 * A_BUF + 2 * B_BUF) * 4)   // 55296

__device__ __forceinline__ void cp16(void* dst, const void* src) {
    uint32_t d = (uint32_t)__cvta_generic_to_shared(dst);
    asm volatile("cp.async.cg.shared.global [%0], [%1], 16;" :: "r"(d), "l"(src));
}

__device__ __forceinline__ void mma_tf32(float* d, const uint32_t* a, const uint32_t* b) {
    asm volatile(
        "mma.sync.aligned.m16n8k8.row.col.f32.tf32.tf32.f32 "
        "{%0,%1,%2,%3},{%4,%5,%6,%7},{%8,%9},{%0,%1,%2,%3};"
        : "+f"(d[0]), "+f"(d[1]), "+f"(d[2]), "+f"(d[3])
        : "r"(a[0]), "r"(a[1]), "r"(a[2]), "r"(a[3]), "r"(b[0]), "r"(b[1]));
}

__global__ __launch_bounds__(256) void gemm_tf32_kernel(
    const float* __restrict__ A, const float* __restrict__ Bw,
    const float* __restrict__ bias, const float* __restrict__ res,
    float* __restrict__ C, int M, int N, int K, int flags)
{
    extern __shared__ float smem[];
    float* As[2] = { smem, smem + A_BUF };
    float* Bs[2] = { smem + 2 * A_BUF, smem + 2 * A_BUF + B_BUF };

    const int t = threadIdx.x;
    const int lane = t & 31;
    const int warp = t >> 5;
    const int wm = warp >> 1;        // 0..3
    const int wn = warp & 1;         // 0..1
    const int r = lane >> 2;         // 0..7
    const int c = lane & 3;          // 0..3

    const int bm = blockIdx.y * GBM;
    const int bn = blockIdx.x * GBN;

    // load mapping
    const int arow = t >> 1;                 // 0..127
    const int aq = (t & 1) * 4;              // base float4 index (4 per thread)
    const int brow = t >> 2;                 // 0..63
    const int bq = (t & 3) * 2;              // base float4 index (2 per thread)

    const float* Abase = A + (size_t)(bm + arow) * K;
    const float* Bbase = Bw + (size_t)(bn + brow) * K;
    float* AsRow[2] = { As[0] + arow * APAD, As[1] + arow * APAD };
    float* BsRow[2] = { Bs[0] + brow * APAD, Bs[1] + brow * APAD };

    float acc[2][4][4];
#pragma unroll
    for (int i = 0; i < 2; i++)
#pragma unroll
        for (int j = 0; j < 4; j++)
#pragma unroll
            for (int l = 0; l < 4; l++) acc[i][j][l] = 0.f;

    const int TK = K >> 5;

    // prologue: load tile 0 into buffer 0
    {
#pragma unroll
        for (int j = 0; j < 4; j++)
            cp16(AsRow[0] + (aq + j) * 4, Abase + (aq + j) * 4);
#pragma unroll
        for (int j = 0; j < 2; j++)
            cp16(BsRow[0] + (bq + j) * 4, Bbase + (bq + j) * 4);
        asm volatile("cp.async.commit_group;");
    }

    for (int kt = 0; kt < TK; kt++) {
        const int cur = kt & 1;
        const int nxt = cur ^ 1;
        if (kt + 1 < TK) {
            const int ko = (kt + 1) * GBK;
#pragma unroll
            for (int j = 0; j < 4; j++)
                cp16(AsRow[nxt] + (aq + j) * 4, Abase + ko + (aq + j) * 4);
#pragma unroll
            for (int j = 0; j < 2; j++)
                cp16(BsRow[nxt] + (bq + j) * 4, Bbase + ko + (bq + j) * 4);
            asm volatile("cp.async.commit_group;");
            asm volatile("cp.async.wait_group 1;");
        } else {
            asm volatile("cp.async.wait_group 0;");
        }
        __syncthreads();

        const float* Ac = As[cur];
        const float* Bc = Bs[cur];
#pragma unroll
        for (int ks = 0; ks < 4; ks++) {
            const int k0 = ks * 8;
            uint32_t afr[2][4];
#pragma unroll
            for (int mt = 0; mt < 2; mt++) {
                const int mb = wm * 32 + mt * 16;
                afr[mt][0] = __float_as_uint(Ac[(mb + r) * APAD + k0 + c]);
                afr[mt][1] = __float_as_uint(Ac[(mb + r + 8) * APAD + k0 + c]);
                afr[mt][2] = __float_as_uint(Ac[(mb + r) * APAD + k0 + c + 4]);
                afr[mt][3] = __float_as_uint(Ac[(mb + r + 8) * APAD + k0 + c + 4]);
            }
            uint32_t bfr[4][2];
#pragma unroll
            for (int nt = 0; nt < 4; nt++) {
                const int nb = wn * 32 + nt * 8;
                bfr[nt][0] = __float_as_uint(Bc[(nb + r) * APAD + k0 + c]);
                bfr[nt][1] = __float_as_uint(Bc[(nb + r) * APAD + k0 + c + 4]);
            }
#pragma unroll
            for (int mt = 0; mt < 2; mt++)
#pragma unroll
                for (int nt = 0; nt < 4; nt++)
                    mma_tf32(acc[mt][nt], afr[mt], bfr[nt]);
        }
        __syncthreads();
    }

    // epilogue
#pragma unroll
    for (int mt = 0; mt < 2; mt++) {
        const int m0 = bm + wm * 32 + mt * 16 + r;
#pragma unroll
        for (int nt = 0; nt < 4; nt++) {
            const int n0 = bn + wn * 32 + nt * 8 + c * 2;
#pragma unroll
            for (int e = 0; e < 4; e++) {
                const int m = m0 + (e >> 1) * 8;
                const int n = n0 + (e & 1);
                float v = acc[mt][nt][e] + bias[n];
                if (flags & EF_RELU) v = fmaxf(v, 0.f);
                if (flags & EF_RES)  v += res[(size_t)m * N + n];
                if (flags & EF_ROUND) v = tf32_rna(v);
                if (flags & EF_HEADOUT) {
                    const int s = m >> 1;       // BATCH == 2
                    const int bi = m & 1;
                    const int h = n >> 6;
                    const int hd = n & 63;
                    C[(((size_t)(bi * NHEAD + h)) * S_LEN + s) * HDIM + hd] = v;
                } else {
                    C[(size_t)m * N + n] = v;
                }
            }
        }
    }
}

// ---------------- sparse attention, 2 threads per query ----------------
// Q,K,V: [B*H, S, 64]. O: [S, B, D], tf32-rounded.
// allowed(j|i) = |j-i| <= 5  OR  j % 10 == 0. softmax with fixed max=0 (scores bounded).
#define AQ_PER_BLOCK 64
#define STRIDED_KEYS 205   // ceil(2048/10)

__global__ __launch_bounds__(128) void attn2_kernel(
    const float* __restrict__ Q, const float* __restrict__ K,
    const float* __restrict__ V, float* __restrict__ O)
{
    __shared__ float sK[16 * 64];
    __shared__ float sV[16 * 64];

    const int t = threadIdx.x;
    const int bh = blockIdx.y;
    const int qi = blockIdx.x * AQ_PER_BLOCK + (t >> 1);
    const int half = t & 1;
    const int dimbase = half * 32;
    const size_t base = (size_t)bh * S_LEN;

    float4 q[8];
    const float4* qp = (const float4*)(Q + (base + qi) * HDIM + dimbase);
#pragma unroll
    for (int f = 0; f < 8; f++) q[f] = qp[f];

    float4 acc[8];
#pragma unroll
    for (int f = 0; f < 8; f++) acc[f] = make_float4(0.f, 0.f, 0.f, 0.f);
    float lsum = 0.f;

    // ---- strided keys (shared by all queries in the head) via smem tiles ----
    for (int cb = 0; cb < STRIDED_KEYS; cb += 16) {
        const int cnt = min(16, STRIDED_KEYS - cb);
        __syncthreads();
        for (int idx = t; idx < cnt * 16; idx += 128) {
            const int kk = idx >> 4;
            const int f4 = idx & 15;
            const int j = (cb + kk) * 10;
            ((float4*)sK)[kk * 16 + f4] = ((const float4*)(K + (base + j) * HDIM))[f4];
            ((float4*)sV)[kk * 16 + f4] = ((const float4*)(V + (base + j) * HDIM))[f4];
        }
        __syncthreads();
        for (int kk = 0; kk < cnt; kk++) {
            const float4* kp = (const float4*)(sK + kk * 64 + dimbase);
            float p = 0.f;
#pragma unroll
            for (int f = 0; f < 8; f++) {
                float4 kv = kp[f];
                p += q[f].x * kv.x + q[f].y * kv.y + q[f].z * kv.z + q[f].w * kv.w;
            }
            p += __shfl_xor_sync(0xffffffffu, p, 1);
            const float e = __expf(p * 0.125f);
            lsum += e;
            const float4* vp = (const float4*)(sV + kk * 64 + dimbase);
#pragma unroll
            for (int f = 0; f < 8; f++) {
                float4 vv = vp[f];
                acc[f].x += e * vv.x; acc[f].y += e * vv.y;
                acc[f].z += e * vv.z; acc[f].w += e * vv.w;
            }
        }
    }

    // ---- band keys (|j - i| <= 5, excluding j % 10 == 0) via gmem ----
#pragma unroll
    for (int dj = -WWIN; dj <= WWIN; dj++) {
        const int j = qi + dj;
        const bool valid = (j >= 0) && (j < S_LEN) && (j % 10 != 0);
        const int jc = min(max(j, 0), S_LEN - 1);
        const float4* kp = (const float4*)(K + (base + jc) * HDIM + dimbase);
        float p = 0.f;
#pragma unroll
        for (int f = 0; f < 8; f++) {
            float4 kv = kp[f];
            p += q[f].x * kv.x + q[f].y * kv.y + q[f].z * kv.z + q[f].w * kv.w;
        }
        p += __shfl_xor_sync(0xffffffffu, p, 1);
        const float e = valid ? __expf(p * 0.125f) : 0.f;
        lsum += e;
        const float4* vp = (const float4*)(V + (base + jc) * HDIM + dimbase);
#pragma unroll
        for (int f = 0; f < 8; f++) {
            float4 vv = vp[f];
            acc[f].x += e * vv.x; acc[f].y += e * vv.y;
            acc[f].z += e * vv.z; acc[f].w += e * vv.w;
        }
    }

    const float inv = 1.f / lsum;
    const int b = bh >> 3;     // NHEAD == 8
    const int h = bh & 7;
    float4* op = (float4*)(O + ((size_t)qi * BATCH + b) * DMODEL + h * HDIM + dimbase);
#pragma unroll
    for (int f = 0; f < 8; f++) {
        float4 o;
        o.x = tf32_rna(acc[f].x * inv);
        o.y = tf32_rna(acc[f].y * inv);
        o.z = tf32_rna(acc[f].z * inv);
        o.w = tf32_rna(acc[f].w * inv);
        op[f] = o;
    }
}

// ---------------- layernorm, block per row (dual output: full + tf32) ----------------
__global__ __launch_bounds__(128) void ln_kernel(
    const float* __restrict__ in, const float* __restrict__ g,
    const float* __restrict__ b, float* __restrict__ out,
    float* __restrict__ out_r)
{
    const int row = blockIdx.x;
    const int t = threadIdx.x;
    const float4 v = ((const float4*)(in + (size_t)row * DMODEL))[t];

    float s  = v.x + v.y + v.z + v.w;
    float ss = v.x * v.x + v.y * v.y + v.z * v.z + v.w * v.w;
#pragma unroll
    for (int off = 16; off; off >>= 1) {
        s  += __shfl_xor_sync(0xffffffffu, s, off);
        ss += __shfl_xor_sync(0xffffffffu, ss, off);
    }
    __shared__ float red[8];
    const int wid = t >> 5;
    if ((t & 31) == 0) { red[wid] = s; red[4 + wid] = ss; }
    __syncthreads();
    s  = red[0] + red[1] + red[2] + red[3];
    ss = red[4] + red[5] + red[6] + red[7];

    const float mean = s * (1.f / DMODEL);
    const float var  = ss * (1.f / DMODEL) - mean * mean;
    const float rs = rsqrtf(var + LN_EPS);

    const float4 gg = ((const float4*)g)[t];
    const float4 bb = ((const float4*)b)[t];
    float4 o;
    o.x = (v.x - mean) * rs * gg.x + bb.x;
    o.y = (v.y - mean) * rs * gg.y + bb.y;
    o.z = (v.z - mean) * rs * gg.z + bb.z;
    o.w = (v.w - mean) * rs * gg.w + bb.w;
    ((float4*)(out + (size_t)row * DMODEL))[t] = o;
    if (out_r) {
        float4 orr;
        orr.x = tf32_rna(o.x); orr.y = tf32_rna(o.y);
        orr.z = tf32_rna(o.z); orr.w = tf32_rna(o.w);
        ((float4*)(out_r + (size_t)row * DMODEL))[t] = orr;
    }
}

// ---------------- launch ----------------
extern "C" void kernel_launch(void* const* d_in, const int* in_sizes, int n_in,
                              void* d_out, int out_size)
{
    const float* x   = (const float*)d_in[0];
    const float* enc = (const float*)d_in[1];
    const float* sa_Wq = (const float*)d_in[2];
    const float* sa_Wk = (const float*)d_in[3];
    const float* sa_Wv = (const float*)d_in[4];
    const float* sa_Wo = (const float*)d_in[5];
    const float* sa_bq = (const float*)d_in[6];
    const float* sa_bk = (const float*)d_in[7];
    const float* sa_bv = (const float*)d_in[8];
    const float* sa_bo = (const float*)d_in[9];
    const float* ca_Wq = (const float*)d_in[10];
    const float* ca_Wk = (const float*)d_in[11];
    const float* ca_Wv = (const float*)d_in[12];
    const float* ca_Wo = (const float*)d_in[13];
    const float* ca_bq = (const float*)d_in[14];
    const float* ca_bk = (const float*)d_in[15];
    const float* ca_bv = (const float*)d_in[16];
    const float* ca_bo = (const float*)d_in[17];
    const float* ff_W1 = (const float*)d_in[18];
    const float* ff_W2 = (const float*)d_in[19];
    const float* ff_b1 = (const float*)d_in[20];
    const float* ff_b2 = (const float*)d_in[21];
    const float* ln1_g = (const float*)d_in[22];
    const float* ln1_b = (const float*)d_in[23];
    const float* ln2_g = (const float*)d_in[24];
    const float* ln2_b = (const float*)d_in[25];
    const float* ln3_g = (const float*)d_in[26];
    const float* ln3_b = (const float*)d_in[27];
    float* out = (float*)d_out;

    float *q, *k, *v, *attn, *tmp, *x1, *x2, *ff, *wr, *xr, *encr, *x1r, *x2r;
    cudaGetSymbolAddress((void**)&q, g_q);
    cudaGetSymbolAddress((void**)&k, g_k);
    cudaGetSymbolAddress((void**)&v, g_v);
    cudaGetSymbolAddress((void**)&attn, g_attn);
    cudaGetSymbolAddress((void**)&tmp, g_tmp);
    cudaGetSymbolAddress((void**)&x1, g_x1);
    cudaGetSymbolAddress((void**)&x2, g_x2);
    cudaGetSymbolAddress((void**)&ff, g_ff);
    cudaGetSymbolAddress((void**)&wr, g_wr);
    cudaGetSymbolAddress((void**)&xr, g_xr);
    cudaGetSymbolAddress((void**)&encr, g_encr);
    cudaGetSymbolAddress((void**)&x1r, g_x1r);
    cudaGetSymbolAddress((void**)&x2r, g_x2r);

    // rounded-weight layout inside g_wr
    const int PW = DMODEL * DMODEL;          // 262144
    float* r_saWq = wr + 0 * PW;
    float* r_saWk = wr + 1 * PW;
    float* r_saWv = wr + 2 * PW;
    float* r_saWo = wr + 3 * PW;
    float* r_caWq = wr + 4 * PW;
    float* r_caWk = wr + 5 * PW;
    float* r_caWv = wr + 6 * PW;
    float* r_caWo = wr + 7 * PW;
    float* r_ffW1 = wr + 8 * PW;             // 1048576
    float* r_ffW2 = wr + 8 * PW + FFDIM * DMODEL;

    // convert weights + x + enc to tf32-rounded copies
    CvtArgs ca;
    const float* srcs[12] = { sa_Wq, sa_Wk, sa_Wv, sa_Wo, ca_Wq, ca_Wk, ca_Wv, ca_Wo,
                              ff_W1, ff_W2, x, enc };
    float* dsts[12] = { r_saWq, r_saWk, r_saWv, r_saWo, r_caWq, r_caWk, r_caWv, r_caWo,
                        r_ffW1, r_ffW2, xr, encr };
    int ns[12] = { PW, PW, PW, PW, PW, PW, PW, PW,
                   FFDIM * DMODEL, FFDIM * DMODEL, NTOK * DMODEL, NTOK * DMODEL };
    for (int i = 0; i < 12; i++) { ca.src[i] = srcs[i]; ca.dst[i] = dsts[i]; ca.n4[i] = ns[i] / 4; }

    cudaFuncSetAttribute(gemm_tf32_kernel,
                         cudaFuncAttributeMaxDynamicSharedMemorySize, GEMM_SMEM_BYTES);

    const dim3 blk(256);
    const dim3 gProj(DMODEL / GBN, NTOK / GBM);   // (8, 32)
    const dim3 gFF1(FFDIM / GBN, NTOK / GBM);     // (32, 32)
    const dim3 gAttn(S_LEN / AQ_PER_BLOCK, BATCH * NHEAD);  // (32, 16)

    cvt_kernel<<<dim3(128, 12), blk>>>(ca);

    // ---- self attention ----
    gemm_tf32_kernel<<<gProj, blk, GEMM_SMEM_BYTES>>>(xr, r_saWq, sa_bq, nullptr, q, NTOK, DMODEL, DMODEL, EF_HEADOUT);
    gemm_tf32_kernel<<<gProj, blk, GEMM_SMEM_BYTES>>>(xr, r_saWk, sa_bk, nullptr, k, NTOK, DMODEL, DMODEL, EF_HEADOUT);
    gemm_tf32_kernel<<<gProj, blk, GEMM_SMEM_BYTES>>>(xr, r_saWv, sa_bv, nullptr, v, NTOK, DMODEL, DMODEL, EF_HEADOUT);
    attn2_kernel<<<gAttn, 128>>>(q, k, v, attn);
    gemm_tf32_kernel<<<gProj, blk, GEMM_SMEM_BYTES>>>(attn, r_saWo, sa_bo, x, tmp, NTOK, DMODEL, DMODEL, EF_RES);
    ln_kernel<<<NTOK, 128>>>(tmp, ln1_g, ln1_b, x1, x1r);

    // ---- cross attention ----
    gemm_tf32_kernel<<<gProj, blk, GEMM_SMEM_BYTES>>>(x1r, r_caWq, ca_bq, nullptr, q, NTOK, DMODEL, DMODEL, EF_HEADOUT);
    gemm_tf32_kernel<<<gProj, blk, GEMM_SMEM_BYTES>>>(encr, r_caWk, ca_bk, nullptr, k, NTOK, DMODEL, DMODEL, EF_HEADOUT);
    gemm_tf32_kernel<<<gProj, blk, GEMM_SMEM_BYTES>>>(encr, r_caWv, ca_bv, nullptr, v, NTOK, DMODEL, DMODEL, EF_HEADOUT);
    attn2_kernel<<<gAttn, 128>>>(q, k, v, attn);
    gemm_tf32_kernel<<<gProj, blk, GEMM_SMEM_BYTES>>>(attn, r_caWo, ca_bo, x1, tmp, NTOK, DMODEL, DMODEL, EF_RES);
    ln_kernel<<<NTOK, 128>>>(tmp, ln2_g, ln2_b, x2, x2r);

    // ---- feed forward ----
    gemm_tf32_kernel<<<gFF1, blk, GEMM_SMEM_BYTES>>>(x2r, r_ffW1, ff_b1, nullptr, ff, NTOK, FFDIM, DMODEL, EF_RELU | EF_ROUND);
    gemm_tf32_kernel<<<gProj, blk, GEMM_SMEM_BYTES>>>(ff, r_ffW2, ff_b2, x2, tmp, NTOK, DMODEL, FFDIM, EF_RES);
    ln_kernel<<<NTOK, 128>>>(tmp, ln3_g, ln3_b, out, nullptr);
}